// round 2
// baseline (speedup 1.0000x reference)
#include <cuda_runtime.h>
#include <cuda_bf16.h>
#include <math.h>

#define F 64
#define H 128

#define NCAP  65536
#define ECAP  524288
#define RCAP  32768
#define NBLK_E 1024

// ---------------- scratch (static device globals; no allocation) -------------
__device__ float g_h   [(size_t)NCAP * H];
__device__ float g_A   [(size_t)NCAP * H];
__device__ float g_B   [(size_t)NCAP * H];
__device__ float g_aggr[(size_t)NCAP * H];
__device__ float g_rh  [(size_t)RCAP * H];
__device__ float g_th  [(size_t)RCAP * H];
__device__ float g_s   [ECAP];
__device__ float g_partials[NBLK_E];
__device__ unsigned g_max_enc;
__device__ float g_inv;

// monotonic float<->uint encoding for atomicMax over signed floats
__device__ __forceinline__ unsigned fenc(float f) {
    unsigned u = __float_as_uint(f);
    return (u & 0x80000000u) ? ~u : (u | 0x80000000u);
}
__device__ __forceinline__ float fdec(unsigned e) {
    return (e & 0x80000000u) ? __uint_as_float(e ^ 0x80000000u)
                             : __uint_as_float(~e);
}

// ---------------- init: zero aggr, reset max --------------------------------
__global__ void init_kernel(int n_elems) {
    size_t i = (size_t)blockIdx.x * blockDim.x + threadIdx.x;
    size_t stride = (size_t)gridDim.x * blockDim.x;
    for (; i < (size_t)n_elems; i += stride) g_aggr[i] = 0.f;
    if (blockIdx.x == 0 && threadIdx.x == 0) g_max_enc = 0u;
}

// ---------------- generic fp32 GEMM: Y[M,128] = X[M,K] @ W[K,128] + bias ----
// block tile 64 rows x 128 cols, BK=32. 256 threads.
// thread: 4 cols (c, c+32, c+64, c+96) x 8 rows -> 32 accumulators.
__global__ void gemm128_kernel(const float* __restrict__ X,
                               const float* __restrict__ W,
                               const float* __restrict__ bias,
                               float* __restrict__ Y, int M, int K) {
    __shared__ float Xs[64][32];
    __shared__ float Ws[32][128];
    int tid  = threadIdx.x;
    int c    = tid & 31;     // base col
    int rb   = tid >> 5;     // row band 0..7 (warp-uniform)
    int row0 = blockIdx.x * 64;

    float acc[4][8];
#pragma unroll
    for (int j = 0; j < 4; j++)
#pragma unroll
        for (int r = 0; r < 8; r++) acc[j][r] = 0.f;

    for (int k0 = 0; k0 < K; k0 += 32) {
#pragma unroll
        for (int i = 0; i < 8; i++) {              // 64x32 = 2048 elems
            int idx = tid + i * 256;
            int r = idx >> 5, kk = idx & 31;
            int row = row0 + r;
            Xs[r][kk] = (row < M) ? X[(size_t)row * K + k0 + kk] : 0.f;
        }
#pragma unroll
        for (int i = 0; i < 16; i++) {             // 32x128 = 4096 elems
            int idx = tid + i * 256;
            int kr = idx >> 7, cc = idx & 127;
            Ws[kr][cc] = W[(size_t)(k0 + kr) * 128 + cc];
        }
        __syncthreads();
#pragma unroll
        for (int kk = 0; kk < 32; kk++) {
            float xv[8];
#pragma unroll
            for (int r = 0; r < 8; r++) xv[r] = Xs[rb * 8 + r][kk];
#pragma unroll
            for (int j = 0; j < 4; j++) {
                float w = Ws[kk][c + 32 * j];
#pragma unroll
                for (int r = 0; r < 8; r++) acc[j][r] += xv[r] * w;
            }
        }
        __syncthreads();
    }
#pragma unroll
    for (int j = 0; j < 4; j++) {
        float bj = bias ? bias[c + 32 * j] : 0.f;
#pragma unroll
        for (int r = 0; r < 8; r++) {
            int row = row0 + rb * 8 + r;
            if (row < M) Y[(size_t)row * 128 + c + 32 * j] = acc[j][r] + bj;
        }
    }
}

// ---------------- edge scores: s[e] = relu(A[dst]+B[src]+dist@Wd+b1)@w2+b2 --
// warp per edge (grid-stride). Tracks global max via encoded atomicMax.
__global__ void edge_score_kernel(const int* __restrict__ ei,
                                  const float* __restrict__ pos,
                                  const float* __restrict__ W1,
                                  const float* __restrict__ b1,
                                  const float* __restrict__ w2,
                                  const float* __restrict__ b2,
                                  int E) {
    __shared__ float sWd[3][H];
    __shared__ float sB1[H];
    __shared__ float sW2[H];
    int tid = threadIdx.x;
    for (int i = tid; i < H; i += blockDim.x) {
        sWd[0][i] = W1[(size_t)(2 * H + 0) * H + i];
        sWd[1][i] = W1[(size_t)(2 * H + 1) * H + i];
        sWd[2][i] = W1[(size_t)(2 * H + 2) * H + i];
        sB1[i] = b1[i];
        sW2[i] = w2[i];
    }
    __syncthreads();

    int lane = tid & 31;
    int warp = blockIdx.x * (blockDim.x >> 5) + (tid >> 5);
    int nwarps = gridDim.x * (blockDim.x >> 5);
    float b2v = *b2;
    float lmax = __int_as_float(0xff800000);  // -inf

    for (int e = warp; e < E; e += nwarps) {
        int src = ei[e];
        int dst = ei[E + e];
        float d0 = pos[dst * 3 + 0] - pos[src * 3 + 0];
        float d1 = pos[dst * 3 + 1] - pos[src * 3 + 1];
        float d2 = pos[dst * 3 + 2] - pos[src * 3 + 2];
        int c = lane * 4;
        float4 a = *(const float4*)(g_A + (size_t)dst * H + c);
        float4 b = *(const float4*)(g_B + (size_t)src * H + c);
        float part = 0.f;
        float av[4] = {a.x, a.y, a.z, a.w};
        float bv[4] = {b.x, b.y, b.z, b.w};
#pragma unroll
        for (int i = 0; i < 4; i++) {
            int cc = c + i;
            float z = av[i] + bv[i] + d0 * sWd[0][cc] + d1 * sWd[1][cc]
                      + d2 * sWd[2][cc] + sB1[cc];
            part += fmaxf(z, 0.f) * sW2[cc];
        }
#pragma unroll
        for (int off = 16; off; off >>= 1)
            part += __shfl_xor_sync(0xffffffffu, part, off);
        float s = part + b2v;
        if (lane == 0) g_s[e] = s;
        lmax = fmaxf(lmax, s);
    }
    if (lane == 0 && lmax > __int_as_float(0xff800000))
        atomicMax(&g_max_enc, fenc(lmax));
}

// ---------------- exp(s - max), per-block partial sums ----------------------
__global__ void exp_sum_kernel(int E) {
    __shared__ float red[256];
    float mx = fdec(g_max_enc);
    float local = 0.f;
    int stride = gridDim.x * blockDim.x;
    for (int i = blockIdx.x * blockDim.x + threadIdx.x; i < E; i += stride) {
        float p = expf(g_s[i] - mx);
        g_s[i] = p;
        local += p;
    }
    red[threadIdx.x] = local;
    __syncthreads();
    for (int off = 128; off; off >>= 1) {
        if (threadIdx.x < off) red[threadIdx.x] += red[threadIdx.x + off];
        __syncthreads();
    }
    if (threadIdx.x == 0) g_partials[blockIdx.x] = red[0];
}

__global__ void finalize_kernel() {
    __shared__ float red[NBLK_E];
    red[threadIdx.x] = g_partials[threadIdx.x];
    __syncthreads();
    for (int off = NBLK_E / 2; off; off >>= 1) {
        if (threadIdx.x < off) red[threadIdx.x] += red[threadIdx.x + off];
        __syncthreads();
    }
    if (threadIdx.x == 0) g_inv = 1.f / red[0];
}

// ---------------- scatter: aggr[dst] += h[src] * att ------------------------
__global__ void scatter_kernel(const int* __restrict__ ei, int E) {
    float inv = g_inv;
    int lane = threadIdx.x & 31;
    int warp = blockIdx.x * (blockDim.x >> 5) + (threadIdx.x >> 5);
    int nwarps = gridDim.x * (blockDim.x >> 5);
    for (int e = warp; e < E; e += nwarps) {
        int src = ei[e];
        int dst = ei[E + e];
        float att = g_s[e] * inv;
        int c = lane * 4;
        float4 hx = *(const float4*)(g_h + (size_t)src * H + c);
        float* dp = g_aggr + (size_t)dst * H + c;
        atomicAdd(dp + 0, hx.x * att);
        atomicAdd(dp + 1, hx.y * att);
        atomicAdd(dp + 2, hx.z * att);
        atomicAdd(dp + 3, hx.w * att);
    }
}

// ---------------- head MLP: out = relu(X@W1 + b1) @ w2 + b2 -----------------
// warp per row; lane owns cols (lane, lane+32) of 64 hidden units.
__global__ void head_kernel(const float* __restrict__ X,
                            const float* __restrict__ W1,   // [128,64]
                            const float* __restrict__ b1,   // [64]
                            const float* __restrict__ w2,   // [64]
                            const float* __restrict__ b2,   // [1]
                            float* __restrict__ out, int M) {
    __shared__ float W1s[128 * 64];
    __shared__ float b1s[64], w2s[64];
    __shared__ float xs[8][128];
    int tid = threadIdx.x;
    for (int i = tid; i < 128 * 64; i += 256) W1s[i] = W1[i];
    if (tid < 64) { b1s[tid] = b1[tid]; w2s[tid] = w2[tid]; }
    __syncthreads();

    int lane = tid & 31;
    int w = tid >> 5;
    int warp = blockIdx.x * 8 + w;
    int nw = gridDim.x * 8;
    float b2v = *b2;

    for (int row = warp; row < M; row += nw) {
        float4 v = *(const float4*)(X + (size_t)row * 128 + lane * 4);
        *(float4*)(&xs[w][lane * 4]) = v;
        __syncwarp();
        float h0 = 0.f, h1 = 0.f;
#pragma unroll
        for (int k = 0; k < 128; k++) {
            float xk = xs[w][k];
            h0 += xk * W1s[k * 64 + lane];
            h1 += xk * W1s[k * 64 + lane + 32];
        }
        h0 = fmaxf(h0 + b1s[lane], 0.f);
        h1 = fmaxf(h1 + b1s[lane + 32], 0.f);
        float p = h0 * w2s[lane] + h1 * w2s[lane + 32];
#pragma unroll
        for (int off = 16; off; off >>= 1)
            p += __shfl_xor_sync(0xffffffffu, p, off);
        if (lane == 0) out[row] = p + b2v;
        __syncwarp();
    }
}

// ---------------- launch ----------------------------------------------------
extern "C" void kernel_launch(void* const* d_in, const int* in_sizes, int n_in,
                              void* d_out, int out_size) {
    const float* mol_x      = (const float*)d_in[0];
    const float* pos        = (const float*)d_in[1];
    const float* reaction_x = (const float*)d_in[2];
    const float* target_x   = (const float*)d_in[3];
    const int*   edge_index = (const int*)  d_in[4];
    const float* W_node = (const float*)d_in[5];
    const float* b_node = (const float*)d_in[6];
    const float* W_att1 = (const float*)d_in[7];
    const float* b_att1 = (const float*)d_in[8];
    const float* W_att2 = (const float*)d_in[9];
    const float* b_att2 = (const float*)d_in[10];
    const float* W_upd  = (const float*)d_in[11];
    const float* b_upd  = (const float*)d_in[12];
    const float* Wy1 = (const float*)d_in[13];
    const float* by1 = (const float*)d_in[14];
    const float* Wy2 = (const float*)d_in[15];
    const float* by2 = (const float*)d_in[16];
    const float* Wa1 = (const float*)d_in[17];
    const float* ba1 = (const float*)d_in[18];
    const float* Wa2 = (const float*)d_in[19];
    const float* ba2 = (const float*)d_in[20];

    int N  = in_sizes[1] / 3;
    int E  = in_sizes[4] / 2;
    int NR = in_sizes[2] / F;
    int NT = in_sizes[3] / F;

    float *h, *A, *B, *aggr, *rh, *th;
    cudaGetSymbolAddress((void**)&h,    g_h);
    cudaGetSymbolAddress((void**)&A,    g_A);
    cudaGetSymbolAddress((void**)&B,    g_B);
    cudaGetSymbolAddress((void**)&aggr, g_aggr);
    cudaGetSymbolAddress((void**)&rh,   g_rh);
    cudaGetSymbolAddress((void**)&th,   g_th);

    float* out = (float*)d_out;
    float* out_yield = out;
    float* out_act   = out + NR;
    float* out_feats = out + NR + NT;

    // 1) zero aggr, reset softmax max
    init_kernel<<<2048, 256>>>(N * H);
    // 2) h = mol_x @ W_node + b_node
    gemm128_kernel<<<(N + 63) / 64, 256>>>(mol_x, W_node, b_node, h, N, F);
    // 3,4) A = h @ W_att1[0:128], B = h @ W_att1[128:256]
    gemm128_kernel<<<(N + 63) / 64, 256>>>(h, W_att1,                 nullptr, A, N, H);
    gemm128_kernel<<<(N + 63) / 64, 256>>>(h, W_att1 + (size_t)H * H, nullptr, B, N, H);
    // 5) edge scores + global max
    edge_score_kernel<<<4096, 256>>>(edge_index, pos, W_att1, b_att1,
                                     W_att2, b_att2, E);
    // 6,7) softmax denominator
    exp_sum_kernel<<<NBLK_E, 256>>>(E);
    finalize_kernel<<<1, NBLK_E>>>();
    // 8) scatter messages
    scatter_kernel<<<4096, 256>>>(edge_index, E);
    // 9) mol_feats = aggr @ W_upd + b_upd  -> directly into output
    gemm128_kernel<<<(N + 63) / 64, 256>>>(aggr, W_upd, b_upd, out_feats, N, H);
    // 10,11) yield head
    gemm128_kernel<<<(NR + 63) / 64, 256>>>(reaction_x, W_node, b_node, rh, NR, F);
    head_kernel<<<512, 256>>>(rh, Wy1, by1, Wy2, by2, out_yield, NR);
    // 12,13) activity head
    gemm128_kernel<<<(NT + 63) / 64, 256>>>(target_x, W_node, b_node, th, NT, F);
    head_kernel<<<512, 256>>>(th, Wa1, ba1, Wa2, ba2, out_act, NT);
}

// round 3
// speedup vs baseline: 1.7118x; 1.7118x over previous
#include <cuda_runtime.h>
#include <cuda_bf16.h>
#include <math.h>

#define F 64
#define H 128

#define NCAP  65536
#define ECAP  524288
#define RCAP  32768
#define NBLK_E 1024

// ---------------- scratch (static device globals; no allocation) -------------
__device__ float g_h   [(size_t)NCAP * H];
__device__ float g_A   [(size_t)NCAP * H];
__device__ float g_B   [(size_t)NCAP * H];
__device__ float g_aggr[(size_t)NCAP * H];
__device__ float g_rh  [(size_t)RCAP * H];
__device__ float g_th  [(size_t)RCAP * H];
__device__ float g_s   [ECAP];
__device__ float g_partials[NBLK_E];
__device__ unsigned g_max_enc;
__device__ float g_inv;

// monotonic float<->uint encoding for atomicMax over signed floats
__device__ __forceinline__ unsigned fenc(float f) {
    unsigned u = __float_as_uint(f);
    return (u & 0x80000000u) ? ~u : (u | 0x80000000u);
}
__device__ __forceinline__ float fdec(unsigned e) {
    return (e & 0x80000000u) ? __uint_as_float(e ^ 0x80000000u)
                             : __uint_as_float(~e);
}

__device__ __forceinline__ unsigned f2tf(float f) {
    unsigned r;
    asm("cvt.rna.tf32.f32 %0, %1;" : "=r"(r) : "f"(f));
    return r;
}

__device__ __forceinline__ void mma_tf32(float* d, const unsigned* a,
                                         const unsigned* b) {
    asm volatile(
        "mma.sync.aligned.m16n8k8.row.col.f32.tf32.tf32.f32 "
        "{%0,%1,%2,%3}, {%4,%5,%6,%7}, {%8,%9}, {%0,%1,%2,%3};"
        : "+f"(d[0]), "+f"(d[1]), "+f"(d[2]), "+f"(d[3])
        : "r"(a[0]), "r"(a[1]), "r"(a[2]), "r"(a[3]), "r"(b[0]), "r"(b[1]));
}

// ---------------- init: zero aggr, reset max --------------------------------
__global__ void init_kernel(int n_elems) {
    size_t i = (size_t)blockIdx.x * blockDim.x + threadIdx.x;
    size_t stride = (size_t)gridDim.x * blockDim.x;
    for (; i < (size_t)n_elems; i += stride) g_aggr[i] = 0.f;
    if (blockIdx.x == 0 && threadIdx.x == 0) g_max_enc = 0u;
}

// ---------------- tf32 tensor-core GEMM: Y[M,128] = X[M,K]@W[K,128]+bias ----
// Block tile 128x128, BK=32, 256 threads (8 warps), warp tile 32x64.
// Xs pitch 36 and Ws pitch 136 chosen so both the store pattern and the
// mma fragment-load pattern are bank-conflict-free.
#define BM 128
#define BK 32
#define XP 36
#define WP 136

__global__ __launch_bounds__(256, 2)
void gemm_tf32_kernel(const float* __restrict__ X,
                      const float* __restrict__ W,
                      const float* __restrict__ bias,
                      float* __restrict__ Y, int M, int K) {
    __shared__ float Xs[BM][XP];   // 18432 B
    __shared__ float Ws[BK][WP];   // 17408 B

    int tid  = threadIdx.x;
    int lane = tid & 31;
    int warp = tid >> 5;
    int wm   = warp & 3;           // 4 warps along M
    int wn   = warp >> 2;          // 2 warps along N
    int g    = lane >> 2;          // groupID
    int tig  = lane & 3;           // thread-in-group
    int m0   = blockIdx.x * BM;

    float acc[2][8][4];
#pragma unroll
    for (int mt = 0; mt < 2; mt++)
#pragma unroll
        for (int nt = 0; nt < 8; nt++)
#pragma unroll
            for (int r = 0; r < 4; r++) acc[mt][nt][r] = 0.f;

    for (int k0 = 0; k0 < K; k0 += BK) {
        // load X tile (128 x 32), row-major, lane = k -> conflict-free STS
#pragma unroll
        for (int i = 0; i < 16; i++) {
            int m = (tid >> 5) + i * 8;
            int row = m0 + m;
            Xs[m][lane] = (row < M) ? X[(size_t)row * K + k0 + lane] : 0.f;
        }
        // load W tile (32 x 128)
#pragma unroll
        for (int i = 0; i < 16; i++) {
            int kr = (tid >> 7) + i * 2;
            int n  = tid & 127;
            Ws[kr][n] = W[(size_t)(k0 + kr) * 128 + n];
        }
        __syncthreads();

#pragma unroll
        for (int ks = 0; ks < 4; ks++) {
            unsigned bfr[8][2];
#pragma unroll
            for (int nt = 0; nt < 8; nt++) {
                int col = wn * 64 + nt * 8 + g;
                bfr[nt][0] = f2tf(Ws[ks * 8 + tig][col]);
                bfr[nt][1] = f2tf(Ws[ks * 8 + tig + 4][col]);
            }
#pragma unroll
            for (int mt = 0; mt < 2; mt++) {
                int rb = wm * 32 + mt * 16;
                unsigned afr[4];
                afr[0] = f2tf(Xs[rb + g][ks * 8 + tig]);
                afr[1] = f2tf(Xs[rb + g + 8][ks * 8 + tig]);
                afr[2] = f2tf(Xs[rb + g][ks * 8 + tig + 4]);
                afr[3] = f2tf(Xs[rb + g + 8][ks * 8 + tig + 4]);
#pragma unroll
                for (int nt = 0; nt < 8; nt++)
                    mma_tf32(acc[mt][nt], afr, bfr[nt]);
            }
        }
        __syncthreads();
    }

    // epilogue: bias + store (float2 per fragment row)
#pragma unroll
    for (int mt = 0; mt < 2; mt++) {
        int rb = m0 + wm * 32 + mt * 16;
#pragma unroll
        for (int nt = 0; nt < 8; nt++) {
            int col = wn * 64 + nt * 8 + 2 * tig;
            float b0 = bias ? bias[col]     : 0.f;
            float b1 = bias ? bias[col + 1] : 0.f;
            int r0 = rb + g;
            if (r0 < M) {
                float2 v = make_float2(acc[mt][nt][0] + b0, acc[mt][nt][1] + b1);
                *(float2*)(Y + (size_t)r0 * 128 + col) = v;
            }
            int r1 = rb + g + 8;
            if (r1 < M) {
                float2 v = make_float2(acc[mt][nt][2] + b0, acc[mt][nt][3] + b1);
                *(float2*)(Y + (size_t)r1 * 128 + col) = v;
            }
        }
    }
}

// ---------------- edge scores: s[e] = relu(A[dst]+B[src]+dist@Wd+b1)@w2+b2 --
__global__ void edge_score_kernel(const int* __restrict__ ei,
                                  const float* __restrict__ pos,
                                  const float* __restrict__ W1,
                                  const float* __restrict__ b1,
                                  const float* __restrict__ w2,
                                  const float* __restrict__ b2,
                                  int E) {
    __shared__ float sWd[3][H];
    __shared__ float sB1[H];
    __shared__ float sW2[H];
    int tid = threadIdx.x;
    for (int i = tid; i < H; i += blockDim.x) {
        sWd[0][i] = W1[(size_t)(2 * H + 0) * H + i];
        sWd[1][i] = W1[(size_t)(2 * H + 1) * H + i];
        sWd[2][i] = W1[(size_t)(2 * H + 2) * H + i];
        sB1[i] = b1[i];
        sW2[i] = w2[i];
    }
    __syncthreads();

    int lane = tid & 31;
    int warp = blockIdx.x * (blockDim.x >> 5) + (tid >> 5);
    int nwarps = gridDim.x * (blockDim.x >> 5);
    float b2v = *b2;
    float lmax = __int_as_float(0xff800000);  // -inf

    for (int e = warp; e < E; e += nwarps) {
        int src = ei[e];
        int dst = ei[E + e];
        float d0 = pos[dst * 3 + 0] - pos[src * 3 + 0];
        float d1 = pos[dst * 3 + 1] - pos[src * 3 + 1];
        float d2 = pos[dst * 3 + 2] - pos[src * 3 + 2];
        int c = lane * 4;
        float4 a = *(const float4*)(g_A + (size_t)dst * H + c);
        float4 b = *(const float4*)(g_B + (size_t)src * H + c);
        float part = 0.f;
        float av[4] = {a.x, a.y, a.z, a.w};
        float bv[4] = {b.x, b.y, b.z, b.w};
#pragma unroll
        for (int i = 0; i < 4; i++) {
            int cc = c + i;
            float z = av[i] + bv[i] + d0 * sWd[0][cc] + d1 * sWd[1][cc]
                      + d2 * sWd[2][cc] + sB1[cc];
            part += fmaxf(z, 0.f) * sW2[cc];
        }
#pragma unroll
        for (int off = 16; off; off >>= 1)
            part += __shfl_xor_sync(0xffffffffu, part, off);
        float s = part + b2v;
        if (lane == 0) g_s[e] = s;
        lmax = fmaxf(lmax, s);
    }
    if (lane == 0 && lmax > __int_as_float(0xff800000))
        atomicMax(&g_max_enc, fenc(lmax));
}

// ---------------- exp(s - max), per-block partial sums ----------------------
__global__ void exp_sum_kernel(int E) {
    __shared__ float red[256];
    float mx = fdec(g_max_enc);
    float local = 0.f;
    int stride = gridDim.x * blockDim.x;
    for (int i = blockIdx.x * blockDim.x + threadIdx.x; i < E; i += stride) {
        float p = expf(g_s[i] - mx);
        g_s[i] = p;
        local += p;
    }
    red[threadIdx.x] = local;
    __syncthreads();
    for (int off = 128; off; off >>= 1) {
        if (threadIdx.x < off) red[threadIdx.x] += red[threadIdx.x + off];
        __syncthreads();
    }
    if (threadIdx.x == 0) g_partials[blockIdx.x] = red[0];
}

__global__ void finalize_kernel() {
    __shared__ float red[NBLK_E];
    red[threadIdx.x] = g_partials[threadIdx.x];
    __syncthreads();
    for (int off = NBLK_E / 2; off; off >>= 1) {
        if (threadIdx.x < off) red[threadIdx.x] += red[threadIdx.x + off];
        __syncthreads();
    }
    if (threadIdx.x == 0) g_inv = 1.f / red[0];
}

// ---------------- scatter: aggr[dst] += h[src] * att (vector red) -----------
__global__ void scatter_kernel(const int* __restrict__ ei, int E) {
    float inv = g_inv;
    int lane = threadIdx.x & 31;
    int warp = blockIdx.x * (blockDim.x >> 5) + (threadIdx.x >> 5);
    int nwarps = gridDim.x * (blockDim.x >> 5);
    for (int e = warp; e < E; e += nwarps) {
        int src = ei[e];
        int dst = ei[E + e];
        float att = g_s[e] * inv;
        int c = lane * 4;
        float4 hx = *(const float4*)(g_h + (size_t)src * H + c);
        float* dp = g_aggr + (size_t)dst * H + c;
        asm volatile("red.global.add.v4.f32 [%0], {%1,%2,%3,%4};"
                     :: "l"(dp), "f"(hx.x * att), "f"(hx.y * att),
                        "f"(hx.z * att), "f"(hx.w * att)
                     : "memory");
    }
}

// ---------------- head MLP: out = relu(X@W1 + b1) @ w2 + b2 -----------------
__global__ void head_kernel(const float* __restrict__ X,
                            const float* __restrict__ W1,   // [128,64]
                            const float* __restrict__ b1,   // [64]
                            const float* __restrict__ w2,   // [64]
                            const float* __restrict__ b2,   // [1]
                            float* __restrict__ out, int M) {
    __shared__ float W1s[128 * 64];
    __shared__ float b1s[64], w2s[64];
    __shared__ float xs[8][128];
    int tid = threadIdx.x;
    for (int i = tid; i < 128 * 64; i += 256) W1s[i] = W1[i];
    if (tid < 64) { b1s[tid] = b1[tid]; w2s[tid] = w2[tid]; }
    __syncthreads();

    int lane = tid & 31;
    int w = tid >> 5;
    int warp = blockIdx.x * 8 + w;
    int nw = gridDim.x * 8;
    float b2v = *b2;

    for (int row = warp; row < M; row += nw) {
        float4 v = *(const float4*)(X + (size_t)row * 128 + lane * 4);
        *(float4*)(&xs[w][lane * 4]) = v;
        __syncwarp();
        float h0 = 0.f, h1 = 0.f;
#pragma unroll
        for (int k = 0; k < 128; k++) {
            float xk = xs[w][k];
            h0 += xk * W1s[k * 64 + lane];
            h1 += xk * W1s[k * 64 + lane + 32];
        }
        h0 = fmaxf(h0 + b1s[lane], 0.f);
        h1 = fmaxf(h1 + b1s[lane + 32], 0.f);
        float p = h0 * w2s[lane] + h1 * w2s[lane + 32];
#pragma unroll
        for (int off = 16; off; off >>= 1)
            p += __shfl_xor_sync(0xffffffffu, p, off);
        if (lane == 0) out[row] = p + b2v;
        __syncwarp();
    }
}

// ---------------- launch ----------------------------------------------------
extern "C" void kernel_launch(void* const* d_in, const int* in_sizes, int n_in,
                              void* d_out, int out_size) {
    const float* mol_x      = (const float*)d_in[0];
    const float* pos        = (const float*)d_in[1];
    const float* reaction_x = (const float*)d_in[2];
    const float* target_x   = (const float*)d_in[3];
    const int*   edge_index = (const int*)  d_in[4];
    const float* W_node = (const float*)d_in[5];
    const float* b_node = (const float*)d_in[6];
    const float* W_att1 = (const float*)d_in[7];
    const float* b_att1 = (const float*)d_in[8];
    const float* W_att2 = (const float*)d_in[9];
    const float* b_att2 = (const float*)d_in[10];
    const float* W_upd  = (const float*)d_in[11];
    const float* b_upd  = (const float*)d_in[12];
    const float* Wy1 = (const float*)d_in[13];
    const float* by1 = (const float*)d_in[14];
    const float* Wy2 = (const float*)d_in[15];
    const float* by2 = (const float*)d_in[16];
    const float* Wa1 = (const float*)d_in[17];
    const float* ba1 = (const float*)d_in[18];
    const float* Wa2 = (const float*)d_in[19];
    const float* ba2 = (const float*)d_in[20];

    int N  = in_sizes[1] / 3;
    int E  = in_sizes[4] / 2;
    int NR = in_sizes[2] / F;
    int NT = in_sizes[3] / F;

    float *h, *A, *B, *aggr, *rh, *th;
    cudaGetSymbolAddress((void**)&h,    g_h);
    cudaGetSymbolAddress((void**)&A,    g_A);
    cudaGetSymbolAddress((void**)&B,    g_B);
    cudaGetSymbolAddress((void**)&aggr, g_aggr);
    cudaGetSymbolAddress((void**)&rh,   g_rh);
    cudaGetSymbolAddress((void**)&th,   g_th);

    float* out = (float*)d_out;
    float* out_yield = out;
    float* out_act   = out + NR;
    float* out_feats = out + NR + NT;

    int gbN  = (N + BM - 1) / BM;
    int gbR  = (NR + BM - 1) / BM;
    int gbT  = (NT + BM - 1) / BM;

    // 1) zero aggr, reset softmax max
    init_kernel<<<2048, 256>>>(N * H);
    // 2) h = mol_x @ W_node + b_node
    gemm_tf32_kernel<<<gbN, 256>>>(mol_x, W_node, b_node, h, N, F);
    // 3,4) A = h @ W_att1[0:128], B = h @ W_att1[128:256]
    gemm_tf32_kernel<<<gbN, 256>>>(h, W_att1,                 nullptr, A, N, H);
    gemm_tf32_kernel<<<gbN, 256>>>(h, W_att1 + (size_t)H * H, nullptr, B, N, H);
    // 5) edge scores + global max
    edge_score_kernel<<<4096, 256>>>(edge_index, pos, W_att1, b_att1,
                                     W_att2, b_att2, E);
    // 6,7) softmax denominator
    exp_sum_kernel<<<NBLK_E, 256>>>(E);
    finalize_kernel<<<1, NBLK_E>>>();
    // 8) scatter messages
    scatter_kernel<<<4096, 256>>>(edge_index, E);
    // 9) mol_feats = aggr @ W_upd + b_upd  -> directly into output
    gemm_tf32_kernel<<<gbN, 256>>>(aggr, W_upd, b_upd, out_feats, N, H);
    // 10,11) yield head
    gemm_tf32_kernel<<<gbR, 256>>>(reaction_x, W_node, b_node, rh, NR, F);
    head_kernel<<<512, 256>>>(rh, Wy1, by1, Wy2, by2, out_yield, NR);
    // 12,13) activity head
    gemm_tf32_kernel<<<gbT, 256>>>(target_x, W_node, b_node, th, NT, F);
    head_kernel<<<512, 256>>>(th, Wa1, ba1, Wa2, ba2, out_act, NT);
}

// round 4
// speedup vs baseline: 1.8883x; 1.1031x over previous
#include <cuda_runtime.h>
#include <cuda_bf16.h>
#include <math.h>

#define F 64
#define H 128

#define NCAP  65536
#define ECAP  524288
#define RCAP  32768
#define NBLK_E 1024

// ---------------- scratch (static device globals; no allocation) -------------
__device__ float g_h   [(size_t)NCAP * H];
__device__ float g_A   [(size_t)NCAP * H];
__device__ float g_B   [(size_t)NCAP * H];
__device__ float g_aggr[(size_t)NCAP * H];
__device__ float g_rh  [(size_t)RCAP * H];
__device__ float g_th  [(size_t)RCAP * H];
__device__ float g_s   [ECAP];
__device__ float g_partials[NBLK_E];
__device__ unsigned g_max_enc;
__device__ float g_inv;

__device__ __forceinline__ unsigned fenc(float f) {
    unsigned u = __float_as_uint(f);
    return (u & 0x80000000u) ? ~u : (u | 0x80000000u);
}
__device__ __forceinline__ float fdec(unsigned e) {
    return (e & 0x80000000u) ? __uint_as_float(e ^ 0x80000000u)
                             : __uint_as_float(~e);
}

__device__ __forceinline__ float f2tf(float f) {
    unsigned r;
    asm("cvt.rna.tf32.f32 %0, %1;" : "=r"(r) : "f"(f));
    return __uint_as_float(r);
}

__device__ __forceinline__ void mma_tf32(float* d, const unsigned* a,
                                         const unsigned* b) {
    asm volatile(
        "mma.sync.aligned.m16n8k8.row.col.f32.tf32.tf32.f32 "
        "{%0,%1,%2,%3}, {%4,%5,%6,%7}, {%8,%9}, {%0,%1,%2,%3};"
        : "+f"(d[0]), "+f"(d[1]), "+f"(d[2]), "+f"(d[3])
        : "r"(a[0]), "r"(a[1]), "r"(a[2]), "r"(a[3]), "r"(b[0]), "r"(b[1]));
}

// ---------------- init ------------------------------------------------------
__global__ void init_kernel(int n_elems) {
    size_t i = (size_t)blockIdx.x * blockDim.x + threadIdx.x;
    size_t stride = (size_t)gridDim.x * blockDim.x;
    for (; i < (size_t)n_elems; i += stride) g_aggr[i] = 0.f;
    if (blockIdx.x == 0 && threadIdx.x == 0) g_max_enc = 0u;
}

// ---------------- multi-segment tf32 GEMM -----------------------------------
// Y[M,128] = X[M,K] @ W[K,128] + bias, up to 3 segments per launch.
// Block tile 128x128, BK=32, 256 threads, warp tile 32x64.
// Smem tiles hold tf32-encoded values in k-interleaved layout
// p(k) = (k&3)*8 + (k>>2), pitch 36 -> conflict-free LDS.128 fragment loads.
#define BM 128
#define BK 32
#define PX 36

struct GemmSeg {
    const float* X; const float* W; const float* bias; float* Y;
    int M; int nblk;
};

__global__ __launch_bounds__(256, 2)
void gemm_multi_kernel(GemmSeg s0, GemmSeg s1, GemmSeg s2, int K) {
    __shared__ float Xs[BM][PX];    // 18432 B
    __shared__ float Wt[128][PX];   // 18432 B (W transposed: Wt[n][p(k)])

    int b = blockIdx.x;
    const float* X; const float* W; const float* bias; float* Y; int M; int row0;
    if (b < s0.nblk)                { X=s0.X; W=s0.W; bias=s0.bias; Y=s0.Y; M=s0.M; row0 = b * BM; }
    else if (b < s0.nblk + s1.nblk) { X=s1.X; W=s1.W; bias=s1.bias; Y=s1.Y; M=s1.M; row0 = (b - s0.nblk) * BM; }
    else                            { X=s2.X; W=s2.W; bias=s2.bias; Y=s2.Y; M=s2.M; row0 = (b - s0.nblk - s1.nblk) * BM; }

    int tid  = threadIdx.x;
    int lane = tid & 31;
    int warp = tid >> 5;
    int wm   = warp & 3;
    int wn   = warp >> 2;
    int g    = lane >> 2;
    int tig  = lane & 3;

    // X-load mapping: thread -> rows {xm, xm+32, xm+64, xm+96}, float4 #xq
    int xm = tid >> 3;
    int xq = tid & 7;
    // W-load mapping: thread -> col n, half wh (q0 = 4*wh)
    int wcol = tid & 127;
    int wh   = tid >> 7;

    float acc[2][8][4];
#pragma unroll
    for (int mt = 0; mt < 2; mt++)
#pragma unroll
        for (int nt = 0; nt < 8; nt++)
#pragma unroll
            for (int r = 0; r < 4; r++) acc[mt][nt][r] = 0.f;

    for (int k0 = 0; k0 < K; k0 += BK) {
        // ---- X tile: LDG.128 along k, cvt, scatter-STS into p(k) layout ----
#pragma unroll
        for (int i = 0; i < 4; i++) {
            int m = xm + i * 32;
            int row = row0 + m;
            float4 v = make_float4(0.f, 0.f, 0.f, 0.f);
            if (row < M) v = *(const float4*)(X + (size_t)row * K + k0 + xq * 4);
            Xs[m][0 * 8 + xq] = f2tf(v.x);   // k = 4q+0
            Xs[m][1 * 8 + xq] = f2tf(v.y);   // k = 4q+1
            Xs[m][2 * 8 + xq] = f2tf(v.z);   // k = 4q+2
            Xs[m][3 * 8 + xq] = f2tf(v.w);   // k = 4q+3
        }
        // ---- W tile: gather 4 strided k per j, cvt, STS.128 transposed ----
#pragma unroll
        for (int j = 0; j < 4; j++) {
            float4 sv;
            sv.x = f2tf(W[(size_t)(k0 + 16 * wh +  0 + j) * 128 + wcol]);
            sv.y = f2tf(W[(size_t)(k0 + 16 * wh +  4 + j) * 128 + wcol]);
            sv.z = f2tf(W[(size_t)(k0 + 16 * wh +  8 + j) * 128 + wcol]);
            sv.w = f2tf(W[(size_t)(k0 + 16 * wh + 12 + j) * 128 + wcol]);
            *(float4*)&Wt[wcol][j * 8 + 4 * wh] = sv;
        }
        __syncthreads();

        // ---- MMA: each float4 covers two k-steps (ks even/odd) ----
#pragma unroll
        for (int ks2 = 0; ks2 < 2; ks2++) {
            float4 ar[4];
#pragma unroll
            for (int mt = 0; mt < 2; mt++) {
                ar[2 * mt]     = *(const float4*)&Xs[wm * 32 + mt * 16 + g    ][tig * 8 + ks2 * 4];
                ar[2 * mt + 1] = *(const float4*)&Xs[wm * 32 + mt * 16 + g + 8][tig * 8 + ks2 * 4];
            }
#pragma unroll
            for (int nh = 0; nh < 2; nh++) {
                float4 br[4];
#pragma unroll
                for (int i = 0; i < 4; i++) {
                    int col = wn * 64 + (nh * 4 + i) * 8 + g;
                    br[i] = *(const float4*)&Wt[col][tig * 8 + ks2 * 4];
                }
#pragma unroll
                for (int mt = 0; mt < 2; mt++) {
                    unsigned ae[4] = {__float_as_uint(ar[2*mt].x), __float_as_uint(ar[2*mt+1].x),
                                      __float_as_uint(ar[2*mt].y), __float_as_uint(ar[2*mt+1].y)};
                    unsigned ao[4] = {__float_as_uint(ar[2*mt].z), __float_as_uint(ar[2*mt+1].z),
                                      __float_as_uint(ar[2*mt].w), __float_as_uint(ar[2*mt+1].w)};
#pragma unroll
                    for (int i = 0; i < 4; i++) {
                        unsigned be[2] = {__float_as_uint(br[i].x), __float_as_uint(br[i].y)};
                        unsigned bo[2] = {__float_as_uint(br[i].z), __float_as_uint(br[i].w)};
                        mma_tf32(acc[mt][nh * 4 + i], ae, be);
                        mma_tf32(acc[mt][nh * 4 + i], ao, bo);
                    }
                }
            }
        }
        __syncthreads();
    }

    // ---- epilogue: bias + float2 stores ----
#pragma unroll
    for (int mt = 0; mt < 2; mt++) {
        int rb = row0 + wm * 32 + mt * 16;
#pragma unroll
        for (int nt = 0; nt < 8; nt++) {
            int col = wn * 64 + nt * 8 + 2 * tig;
            float b0 = bias ? bias[col]     : 0.f;
            float b1 = bias ? bias[col + 1] : 0.f;
            int r0 = rb + g;
            if (r0 < M) {
                float2 v = make_float2(acc[mt][nt][0] + b0, acc[mt][nt][1] + b1);
                *(float2*)(Y + (size_t)r0 * 128 + col) = v;
            }
            int r1 = rb + g + 8;
            if (r1 < M) {
                float2 v = make_float2(acc[mt][nt][2] + b0, acc[mt][nt][3] + b1);
                *(float2*)(Y + (size_t)r1 * 128 + col) = v;
            }
        }
    }
}

// ---------------- edge scores -----------------------------------------------
__global__ void edge_score_kernel(const int* __restrict__ ei,
                                  const float* __restrict__ pos,
                                  const float* __restrict__ W1,
                                  const float* __restrict__ b1,
                                  const float* __restrict__ w2,
                                  const float* __restrict__ b2,
                                  int E) {
    __shared__ float sWd[3][H];
    __shared__ float sB1[H];
    __shared__ float sW2[H];
    int tid = threadIdx.x;
    for (int i = tid; i < H; i += blockDim.x) {
        sWd[0][i] = W1[(size_t)(2 * H + 0) * H + i];
        sWd[1][i] = W1[(size_t)(2 * H + 1) * H + i];
        sWd[2][i] = W1[(size_t)(2 * H + 2) * H + i];
        sB1[i] = b1[i];
        sW2[i] = w2[i];
    }
    __syncthreads();

    int lane = tid & 31;
    int warp = blockIdx.x * (blockDim.x >> 5) + (tid >> 5);
    int nwarps = gridDim.x * (blockDim.x >> 5);
    float b2v = *b2;
    float lmax = __int_as_float(0xff800000);

    for (int e = warp; e < E; e += nwarps) {
        int src = ei[e];
        int dst = ei[E + e];
        float d0 = pos[dst * 3 + 0] - pos[src * 3 + 0];
        float d1 = pos[dst * 3 + 1] - pos[src * 3 + 1];
        float d2 = pos[dst * 3 + 2] - pos[src * 3 + 2];
        int c = lane * 4;
        float4 a = *(const float4*)(g_A + (size_t)dst * H + c);
        float4 b = *(const float4*)(g_B + (size_t)src * H + c);
        float part = 0.f;
        float av[4] = {a.x, a.y, a.z, a.w};
        float bv[4] = {b.x, b.y, b.z, b.w};
#pragma unroll
        for (int i = 0; i < 4; i++) {
            int cc = c + i;
            float z = av[i] + bv[i] + d0 * sWd[0][cc] + d1 * sWd[1][cc]
                      + d2 * sWd[2][cc] + sB1[cc];
            part += fmaxf(z, 0.f) * sW2[cc];
        }
#pragma unroll
        for (int off = 16; off; off >>= 1)
            part += __shfl_xor_sync(0xffffffffu, part, off);
        float s = part + b2v;
        if (lane == 0) g_s[e] = s;
        lmax = fmaxf(lmax, s);
    }
    if (lane == 0 && lmax > __int_as_float(0xff800000))
        atomicMax(&g_max_enc, fenc(lmax));
}

// ---------------- softmax denominator ---------------------------------------
__global__ void exp_sum_kernel(int E) {
    __shared__ float red[256];
    float mx = fdec(g_max_enc);
    float local = 0.f;
    int stride = gridDim.x * blockDim.x;
    for (int i = blockIdx.x * blockDim.x + threadIdx.x; i < E; i += stride) {
        float p = expf(g_s[i] - mx);
        g_s[i] = p;
        local += p;
    }
    red[threadIdx.x] = local;
    __syncthreads();
    for (int off = 128; off; off >>= 1) {
        if (threadIdx.x < off) red[threadIdx.x] += red[threadIdx.x + off];
        __syncthreads();
    }
    if (threadIdx.x == 0) g_partials[blockIdx.x] = red[0];
}

__global__ void finalize_kernel() {
    __shared__ float red[NBLK_E];
    red[threadIdx.x] = g_partials[threadIdx.x];
    __syncthreads();
    for (int off = NBLK_E / 2; off; off >>= 1) {
        if (threadIdx.x < off) red[threadIdx.x] += red[threadIdx.x + off];
        __syncthreads();
    }
    if (threadIdx.x == 0) g_inv = 1.f / red[0];
}

// ---------------- scatter ----------------------------------------------------
__global__ void scatter_kernel(const int* __restrict__ ei, int E) {
    float inv = g_inv;
    int lane = threadIdx.x & 31;
    int warp = blockIdx.x * (blockDim.x >> 5) + (threadIdx.x >> 5);
    int nwarps = gridDim.x * (blockDim.x >> 5);
    for (int e = warp; e < E; e += nwarps) {
        int src = ei[e];
        int dst = ei[E + e];
        float att = g_s[e] * inv;
        int c = lane * 4;
        float4 hx = *(const float4*)(g_h + (size_t)src * H + c);
        float* dp = g_aggr + (size_t)dst * H + c;
        asm volatile("red.global.add.v4.f32 [%0], {%1,%2,%3,%4};"
                     :: "l"(dp), "f"(hx.x * att), "f"(hx.y * att),
                        "f"(hx.z * att), "f"(hx.w * att)
                     : "memory");
    }
}

// ---------------- fused dual head MLP ---------------------------------------
__global__ void head2_kernel(const float* X0, const float* W10, const float* b10,
                             const float* w20, const float* b20, float* out0, int M0,
                             const float* X1, const float* W11, const float* b11,
                             const float* w21, const float* b21, float* out1, int M1,
                             int nblk0) {
    __shared__ float W1s[128 * 64];
    __shared__ float b1s[64], w2s[64];
    __shared__ float xs[8][128];

    const float* X; const float* W1; const float* b1; const float* w2;
    const float* b2; float* out; int M; int lb; int nb;
    if (blockIdx.x < nblk0) { X=X0; W1=W10; b1=b10; w2=w20; b2=b20; out=out0; M=M0; lb=blockIdx.x; nb=nblk0; }
    else { X=X1; W1=W11; b1=b11; w2=w21; b2=b21; out=out1; M=M1; lb=blockIdx.x-nblk0; nb=gridDim.x-nblk0; }

    int tid = threadIdx.x;
    for (int i = tid; i < 128 * 64; i += 256) W1s[i] = W1[i];
    if (tid < 64) { b1s[tid] = b1[tid]; w2s[tid] = w2[tid]; }
    __syncthreads();

    int lane = tid & 31;
    int w = tid >> 5;
    int warp = lb * 8 + w;
    int nw = nb * 8;
    float b2v = *b2;

    for (int row = warp; row < M; row += nw) {
        float4 v = *(const float4*)(X + (size_t)row * 128 + lane * 4);
        *(float4*)(&xs[w][lane * 4]) = v;
        __syncwarp();
        float h0 = 0.f, h1 = 0.f;
#pragma unroll
        for (int k = 0; k < 128; k++) {
            float xk = xs[w][k];
            h0 += xk * W1s[k * 64 + lane];
            h1 += xk * W1s[k * 64 + lane + 32];
        }
        h0 = fmaxf(h0 + b1s[lane], 0.f);
        h1 = fmaxf(h1 + b1s[lane + 32], 0.f);
        float p = h0 * w2s[lane] + h1 * w2s[lane + 32];
#pragma unroll
        for (int off = 16; off; off >>= 1)
            p += __shfl_xor_sync(0xffffffffu, p, off);
        if (lane == 0) out[row] = p + b2v;
        __syncwarp();
    }
}

// ---------------- launch ----------------------------------------------------
extern "C" void kernel_launch(void* const* d_in, const int* in_sizes, int n_in,
                              void* d_out, int out_size) {
    const float* mol_x      = (const float*)d_in[0];
    const float* pos        = (const float*)d_in[1];
    const float* reaction_x = (const float*)d_in[2];
    const float* target_x   = (const float*)d_in[3];
    const int*   edge_index = (const int*)  d_in[4];
    const float* W_node = (const float*)d_in[5];
    const float* b_node = (const float*)d_in[6];
    const float* W_att1 = (const float*)d_in[7];
    const float* b_att1 = (const float*)d_in[8];
    const float* W_att2 = (const float*)d_in[9];
    const float* b_att2 = (const float*)d_in[10];
    const float* W_upd  = (const float*)d_in[11];
    const float* b_upd  = (const float*)d_in[12];
    const float* Wy1 = (const float*)d_in[13];
    const float* by1 = (const float*)d_in[14];
    const float* Wy2 = (const float*)d_in[15];
    const float* by2 = (const float*)d_in[16];
    const float* Wa1 = (const float*)d_in[17];
    const float* ba1 = (const float*)d_in[18];
    const float* Wa2 = (const float*)d_in[19];
    const float* ba2 = (const float*)d_in[20];

    int N  = in_sizes[1] / 3;
    int E  = in_sizes[4] / 2;
    int NR = in_sizes[2] / F;
    int NT = in_sizes[3] / F;

    float *h, *A, *B, *aggr, *rh, *th;
    cudaGetSymbolAddress((void**)&h,    g_h);
    cudaGetSymbolAddress((void**)&A,    g_A);
    cudaGetSymbolAddress((void**)&B,    g_B);
    cudaGetSymbolAddress((void**)&aggr, g_aggr);
    cudaGetSymbolAddress((void**)&rh,   g_rh);
    cudaGetSymbolAddress((void**)&th,   g_th);

    float* out = (float*)d_out;
    float* out_yield = out;
    float* out_act   = out + NR;
    float* out_feats = out + NR + NT;

    int gbN = (N  + BM - 1) / BM;
    int gbR = (NR + BM - 1) / BM;
    int gbT = (NT + BM - 1) / BM;

    GemmSeg zero = {nullptr, nullptr, nullptr, nullptr, 0, 0};

    // 1) zero aggr, reset softmax max
    init_kernel<<<2048, 256>>>(N * H);

    // 2) node encoder for all three graphs in ONE launch (K=64)
    {
        GemmSeg s0 = {mol_x,      W_node, b_node, h,  N,  gbN};
        GemmSeg s1 = {reaction_x, W_node, b_node, rh, NR, gbR};
        GemmSeg s2 = {target_x,   W_node, b_node, th, NT, gbT};
        gemm_multi_kernel<<<gbN + gbR + gbT, 256>>>(s0, s1, s2, F);
    }
    // 3) A and B in ONE launch (K=128)
    {
        GemmSeg s0 = {h, W_att1,                 nullptr, A, N, gbN};
        GemmSeg s1 = {h, W_att1 + (size_t)H * H, nullptr, B, N, gbN};
        gemm_multi_kernel<<<gbN * 2, 256>>>(s0, s1, zero, H);
    }
    // 4) edge scores + global max
    edge_score_kernel<<<4096, 256>>>(edge_index, pos, W_att1, b_att1,
                                     W_att2, b_att2, E);
    // 5,6) softmax denominator
    exp_sum_kernel<<<NBLK_E, 256>>>(E);
    finalize_kernel<<<1, NBLK_E>>>();
    // 7) scatter
    scatter_kernel<<<4096, 256>>>(edge_index, E);
    // 8) mol_feats = aggr @ W_upd + b_upd
    {
        GemmSeg s0 = {aggr, W_upd, b_upd, out_feats, N, gbN};
        gemm_multi_kernel<<<gbN, 256>>>(s0, zero, zero, H);
    }
    // 9) both heads in ONE launch
    head2_kernel<<<512, 256>>>(rh, Wy1, by1, Wy2, by2, out_yield, NR,
                               th, Wa1, ba1, Wa2, ba2, out_act, NT, 256);
}